// round 3
// baseline (speedup 1.0000x reference)
#include <cuda_runtime.h>
#include <math.h>

#define NLEV   16
#define TBITS  20
#define TSZ    (1u << TBITS)
#define TMASK  (TSZ - 1u)
#define PRIME  2654435761u

#define THREADS 256

// Shared-memory layout (in floats)
#define SM_W1  0                    // 32*128 = 4096
#define SM_B1  (SM_W1 + 4096)       // 128
#define SM_W2  (SM_B1 + 128)        // 128*128 = 16384
#define SM_B2  (SM_W2 + 16384)      // 128
#define SM_W3  (SM_B2 + 128)        // 128*3 = 384
#define SM_B3  (SM_W3 + 384)        // 3 (+1 pad)
#define SM_TOTAL (SM_B3 + 4)        // 21124 floats = 84496 bytes

__global__ __launch_bounds__(THREADS, 1)
void ngp_fused_kernel(const float2* __restrict__ uv,
                      const float*  __restrict__ tables,
                      const float*  __restrict__ w1, const float* __restrict__ b1,
                      const float*  __restrict__ w2, const float* __restrict__ b2,
                      const float*  __restrict__ w3, const float* __restrict__ b3,
                      float* __restrict__ out, int n)
{
    extern __shared__ float sm[];

    // Stage all weights into shared memory (uniform across CTA; read later as broadcasts)
    for (int i = threadIdx.x; i < 4096;  i += THREADS) sm[SM_W1 + i] = w1[i];
    for (int i = threadIdx.x; i < 128;   i += THREADS) sm[SM_B1 + i] = b1[i];
    for (int i = threadIdx.x; i < 16384; i += THREADS) sm[SM_W2 + i] = w2[i];
    for (int i = threadIdx.x; i < 128;   i += THREADS) sm[SM_B2 + i] = b2[i];
    for (int i = threadIdx.x; i < 384;   i += THREADS) sm[SM_W3 + i] = w3[i];
    if (threadIdx.x < 3) sm[SM_B3 + threadIdx.x] = b3[threadIdx.x];
    __syncthreads();

    int gid = blockIdx.x * THREADS + threadIdx.x;
    if (gid >= n) return;

    float2 p = uv[gid];

    // ---------------- Hash-grid encode: 16 levels -> x[32] ----------------
    float x[2 * NLEV];
#pragma unroll
    for (int l = 0; l < NLEV; l++) {
        const unsigned res = 16u << l;                 // 16 .. 524288 (exact in fp32)
        float px = p.x * (float)res;
        float py = p.y * (float)res;
        float fx = floorf(px), fy = floorf(py);
        float wx = px - fx,    wy = py - fy;
        unsigned cx = (unsigned)(int)fx;
        unsigned cy = (unsigned)(int)fy;

        unsigned i00, i01, i10, i11;
        if ((unsigned long long)(res + 1) * (unsigned long long)(res + 1)
                <= (1ull << TBITS)) {
            // Dense level: row-major linear index (levels 0..5)
            const unsigned rp = res + 1u;
            i00 = cx        + cy        * rp;
            i01 = cx        + (cy + 1u) * rp;
            i10 = (cx + 1u) + cy        * rp;
            i11 = (cx + 1u) + (cy + 1u) * rp;
        } else {
            // Spatial hash (levels 6..15)
            const unsigned hy0 = cy        * PRIME;
            const unsigned hy1 = (cy + 1u) * PRIME;
            i00 = (cx        ^ hy0) & TMASK;
            i01 = (cx        ^ hy1) & TMASK;
            i10 = ((cx + 1u) ^ hy0) & TMASK;
            i11 = ((cx + 1u) ^ hy1) & TMASK;
        }

        const float2* tb = reinterpret_cast<const float2*>(tables) + (size_t)l * TSZ;
        float2 f00 = __ldg(tb + i00);
        float2 f01 = __ldg(tb + i01);
        float2 f10 = __ldg(tb + i10);
        float2 f11 = __ldg(tb + i11);

        float w00 = (1.f - wx) * (1.f - wy);
        float w01 = (1.f - wx) * wy;
        float w10 = wx * (1.f - wy);
        float w11 = wx * wy;

        x[2 * l + 0] = w00 * f00.x + w01 * f01.x + w10 * f10.x + w11 * f11.x;
        x[2 * l + 1] = w00 * f00.y + w01 * f01.y + w10 * f10.y + w11 * f11.y;
    }

    // ---------------- Layer 1: h = relu(x @ w1 + b1), h kept in registers ----------------
    float h[128];
    const float4* w1v = reinterpret_cast<const float4*>(sm + SM_W1);
    const float4* b1v = reinterpret_cast<const float4*>(sm + SM_B1);
#pragma unroll
    for (int jg = 0; jg < 32; jg++) {
        float4 a = b1v[jg];
#pragma unroll
        for (int k = 0; k < 32; k++) {
            float4 w = w1v[k * 32 + jg];
            a.x = fmaf(x[k], w.x, a.x);
            a.y = fmaf(x[k], w.y, a.y);
            a.z = fmaf(x[k], w.z, a.z);
            a.w = fmaf(x[k], w.w, a.w);
        }
        h[4 * jg + 0] = fmaxf(a.x, 0.f);
        h[4 * jg + 1] = fmaxf(a.y, 0.f);
        h[4 * jg + 2] = fmaxf(a.z, 0.f);
        h[4 * jg + 3] = fmaxf(a.w, 0.f);
    }

    // ---------------- Layer 2 (streamed) + Layer 3 accumulation ----------------
    float o0 = sm[SM_B3 + 0];
    float o1 = sm[SM_B3 + 1];
    float o2 = sm[SM_B3 + 2];

    const float4* w2v = reinterpret_cast<const float4*>(sm + SM_W2);
    const float4* b2v = reinterpret_cast<const float4*>(sm + SM_B2);

    for (int jg = 0; jg < 32; jg++) {          // dynamic loop: keeps code size bounded
        float4 a = b2v[jg];
#pragma unroll
        for (int k = 0; k < 128; k++) {        // unrolled: h[k] stays in registers
            float4 w = w2v[k * 32 + jg];
            a.x = fmaf(h[k], w.x, a.x);
            a.y = fmaf(h[k], w.y, a.y);
            a.z = fmaf(h[k], w.z, a.z);
            a.w = fmaf(h[k], w.w, a.w);
        }
        a.x = fmaxf(a.x, 0.f);
        a.y = fmaxf(a.y, 0.f);
        a.z = fmaxf(a.z, 0.f);
        a.w = fmaxf(a.w, 0.f);

        const float* w3r = sm + SM_W3 + jg * 12;   // rows 4jg..4jg+3 of w3[128][3]
        o0 = fmaf(a.x, w3r[0],  o0);
        o1 = fmaf(a.x, w3r[1],  o1);
        o2 = fmaf(a.x, w3r[2],  o2);
        o0 = fmaf(a.y, w3r[3],  o0);
        o1 = fmaf(a.y, w3r[4],  o1);
        o2 = fmaf(a.y, w3r[5],  o2);
        o0 = fmaf(a.z, w3r[6],  o0);
        o1 = fmaf(a.z, w3r[7],  o1);
        o2 = fmaf(a.z, w3r[8],  o2);
        o0 = fmaf(a.w, w3r[9],  o0);
        o1 = fmaf(a.w, w3r[10], o1);
        o2 = fmaf(a.w, w3r[11], o2);
    }

    // ---------------- Sigmoid + store ----------------
    out[3 * gid + 0] = 1.f / (1.f + expf(-o0));
    out[3 * gid + 1] = 1.f / (1.f + expf(-o1));
    out[3 * gid + 2] = 1.f / (1.f + expf(-o2));
}

extern "C" void kernel_launch(void* const* d_in, const int* in_sizes, int n_in,
                              void* d_out, int out_size)
{
    const float2* uv     = (const float2*)d_in[0];
    const float*  tables = (const float*) d_in[1];
    const float*  w1     = (const float*) d_in[2];
    const float*  b1     = (const float*) d_in[3];
    const float*  w2     = (const float*) d_in[4];
    const float*  b2     = (const float*) d_in[5];
    const float*  w3     = (const float*) d_in[6];
    const float*  b3     = (const float*) d_in[7];
    float* out = (float*)d_out;

    int n = in_sizes[0] / 2;

    cudaFuncSetAttribute(ngp_fused_kernel,
                         cudaFuncAttributeMaxDynamicSharedMemorySize,
                         SM_TOTAL * (int)sizeof(float));

    int blocks = (n + THREADS - 1) / THREADS;
    ngp_fused_kernel<<<blocks, THREADS, SM_TOTAL * sizeof(float)>>>(
        uv, tables, w1, b1, w2, b2, w3, b3, out, n);
}

// round 5
// speedup vs baseline: 3.3215x; 3.3215x over previous
#include <cuda_runtime.h>
#include <cuda_bf16.h>
#include <math.h>
#include <stdint.h>

#define NLEV   16
#define TBITS  20
#define TSZ    (1u << TBITS)
#define TMASK  (TSZ - 1u)
#define PRIME  2654435761u

#define CTA    128
#define TILE   128

// padded row strides (bytes) for conflict-free fragment gathers
#define XS   80     // X:   128 rows x 32 bf16 (64B) padded to 80B
#define HS   272    // H:   128 rows x 128 bf16 (256B) padded to 272B
#define W1S  80     // W1^T: 128 rows(n) x 32 k
#define W2S  272    // W2^T: 128 rows(n) x 128 k

#define OFF_W1T  0
#define OFF_W2T  (OFF_W1T + 128 * W1S)      // 10240
#define OFF_X    (OFF_W2T + 128 * W2S)      // 45056
#define OFF_H    (OFF_X   + 128 * XS)       // 55296
#define OFF_B1   (OFF_H   + 128 * HS)       // 90112
#define OFF_B2   (OFF_B1 + 512)
#define OFF_W3   (OFF_B2 + 512)
#define OFF_B3   (OFF_W3 + 1536)
#define DSMEM    (OFF_B3 + 16)              // 92704 B -> 2 CTAs/SM

__device__ __forceinline__ uint32_t pack_bf16x2(float lo, float hi) {
    __nv_bfloat162 p = __float22bfloat162_rn(make_float2(lo, hi));
    return *(uint32_t*)&p;
}

// D += A * B  (m16n8k16, bf16 in, f32 accum)
__device__ __forceinline__ void mma16816(float* d, const uint32_t* a, const uint32_t* b) {
    asm volatile(
        "mma.sync.aligned.m16n8k16.row.col.f32.bf16.bf16.f32 "
        "{%0,%1,%2,%3}, {%4,%5,%6,%7}, {%8,%9}, {%0,%1,%2,%3};"
        : "+f"(d[0]), "+f"(d[1]), "+f"(d[2]), "+f"(d[3])
        : "r"(a[0]), "r"(a[1]), "r"(a[2]), "r"(a[3]), "r"(b[0]), "r"(b[1]));
}

__global__ __launch_bounds__(CTA)
void ngp_mma_kernel(const float2* __restrict__ uv, const float* __restrict__ tables,
                    const float* __restrict__ w1, const float* __restrict__ b1,
                    const float* __restrict__ w2, const float* __restrict__ b2,
                    const float* __restrict__ w3, const float* __restrict__ b3,
                    float* __restrict__ out, int n)
{
    extern __shared__ char smem[];
    const int tid   = threadIdx.x;
    const int wid   = tid >> 5;
    const int lane  = tid & 31;
    const int q     = lane >> 2;      // 0..7  (fragment row/col group)
    const int cpair = lane & 3;       // 0..3  (fragment pair index)

    char* W1T = smem + OFF_W1T;
    char* W2T = smem + OFF_W2T;
    char* X   = smem + OFF_X;
    char* H   = smem + OFF_H;
    float* sb1 = (float*)(smem + OFF_B1);
    float* sb2 = (float*)(smem + OFF_B2);
    float* sw3 = (float*)(smem + OFF_W3);
    float* sb3 = (float*)(smem + OFF_B3);

    // ---- stage weights once per persistent CTA (transposed to [n][k], bf16) ----
    for (int idx = tid; idx < 32 * 128; idx += CTA) {
        int j = idx >> 5, k = idx & 31;   // j = out col (n), k = in (k)
        *(__nv_bfloat16*)(W1T + j * W1S + k * 2) = __float2bfloat16(w1[k * 128 + j]);
    }
    for (int idx = tid; idx < 128 * 128; idx += CTA) {
        int j = idx >> 7, k = idx & 127;
        *(__nv_bfloat16*)(W2T + j * W2S + k * 2) = __float2bfloat16(w2[k * 128 + j]);
    }
    for (int i = tid; i < 128; i += CTA) { sb1[i] = b1[i]; sb2[i] = b2[i]; }
    for (int i = tid; i < 384; i += CTA) sw3[i] = w3[i];
    if (tid < 3) sb3[tid] = b3[tid];
    __syncthreads();

    const int r0b = wid * 32 + q;       // this thread's base row within the tile
    const int ntiles = (n + TILE - 1) / TILE;

    for (int t = blockIdx.x; t < ntiles; t += gridDim.x) {
        const int gid = t * TILE + tid;
        const float2 p = uv[gid < n ? gid : 0];

        // ================= hash-grid encode -> X (bf16, smem) =================
        {
            uint32_t xr[16];
#pragma unroll
            for (int l = 0; l < NLEV; l++) {
                const unsigned res = 16u << l;
                float px = p.x * (float)res, py = p.y * (float)res;
                float fx = floorf(px), fy = floorf(py);
                float wx = px - fx, wy = py - fy;
                unsigned cx = (unsigned)(int)fx, cy = (unsigned)(int)fy;
                unsigned i00, i01, i10, i11;
                if ((unsigned long long)(res + 1) * (res + 1) <= (1ull << TBITS)) {
                    unsigned rp = res + 1u;
                    i00 = cx + cy * rp;        i01 = cx + (cy + 1u) * rp;
                    i10 = cx + 1u + cy * rp;   i11 = cx + 1u + (cy + 1u) * rp;
                } else {
                    unsigned hy0 = cy * PRIME, hy1 = (cy + 1u) * PRIME;
                    i00 = (cx ^ hy0) & TMASK;        i01 = (cx ^ hy1) & TMASK;
                    i10 = ((cx + 1u) ^ hy0) & TMASK; i11 = ((cx + 1u) ^ hy1) & TMASK;
                }
                const float2* tb = (const float2*)tables + (size_t)l * TSZ;
                float2 f00 = __ldg(tb + i00), f01 = __ldg(tb + i01);
                float2 f10 = __ldg(tb + i10), f11 = __ldg(tb + i11);
                float w00 = (1.f - wx) * (1.f - wy), w01 = (1.f - wx) * wy;
                float w10 = wx * (1.f - wy),         w11 = wx * wy;
                float x0 = w00 * f00.x + w01 * f01.x + w10 * f10.x + w11 * f11.x;
                float x1 = w00 * f00.y + w01 * f01.y + w10 * f10.y + w11 * f11.y;
                xr[l] = pack_bf16x2(x0, x1);
            }
            char* xrow = X + tid * XS;
#pragma unroll
            for (int l = 0; l < 16; l++)
                *(uint32_t*)(xrow + l * 4) = xr[l];
        }
        __syncthreads();

        // ================= layer 1: H = relu(X @ W1 + b1) =================
        {
            uint32_t af[2][2][4];
#pragma unroll
            for (int mt = 0; mt < 2; mt++) {
                int r0 = r0b + mt * 16, r1 = r0 + 8;
#pragma unroll
                for (int kt = 0; kt < 2; kt++) {
                    int c0 = kt * 16 + 2 * cpair;
                    af[mt][kt][0] = *(const uint32_t*)(X + r0 * XS + c0 * 2);
                    af[mt][kt][1] = *(const uint32_t*)(X + r1 * XS + c0 * 2);
                    af[mt][kt][2] = *(const uint32_t*)(X + r0 * XS + (c0 + 8) * 2);
                    af[mt][kt][3] = *(const uint32_t*)(X + r1 * XS + (c0 + 8) * 2);
                }
            }
#pragma unroll
            for (int s = 0; s < 4; s++) {
                float d[2][4][4] = {};
#pragma unroll
                for (int kt = 0; kt < 2; kt++) {
                    uint32_t bf[4][2];
#pragma unroll
                    for (int nt = 0; nt < 4; nt++) {
                        int nn = s * 32 + nt * 8 + q;
                        int kk = kt * 16 + 2 * cpair;
                        bf[nt][0] = *(const uint32_t*)(W1T + nn * W1S + kk * 2);
                        bf[nt][1] = *(const uint32_t*)(W1T + nn * W1S + (kk + 8) * 2);
                    }
#pragma unroll
                    for (int nt = 0; nt < 4; nt++) {
                        mma16816(d[0][nt], af[0][kt], bf[nt]);
                        mma16816(d[1][nt], af[1][kt], bf[nt]);
                    }
                }
#pragma unroll
                for (int nt = 0; nt < 4; nt++) {
                    int col = s * 32 + nt * 8 + 2 * cpair;
                    float2 bb = *(const float2*)(sb1 + col);
#pragma unroll
                    for (int mt = 0; mt < 2; mt++) {
                        int r0 = r0b + mt * 16, r1 = r0 + 8;
                        float h00 = fmaxf(d[mt][nt][0] + bb.x, 0.f);
                        float h01 = fmaxf(d[mt][nt][1] + bb.y, 0.f);
                        float h10 = fmaxf(d[mt][nt][2] + bb.x, 0.f);
                        float h11 = fmaxf(d[mt][nt][3] + bb.y, 0.f);
                        *(uint32_t*)(H + r0 * HS + col * 2) = pack_bf16x2(h00, h01);
                        *(uint32_t*)(H + r1 * HS + col * 2) = pack_bf16x2(h10, h11);
                    }
                }
            }
        }
        __syncthreads();

        // ========= layer 2: relu(H @ W2 + b2), fused with layer 3 =========
        float o[4][3] = {};
        {
            uint32_t af[2][8][4];
#pragma unroll
            for (int mt = 0; mt < 2; mt++) {
                int r0 = r0b + mt * 16, r1 = r0 + 8;
#pragma unroll
                for (int kt = 0; kt < 8; kt++) {
                    int c0 = kt * 16 + 2 * cpair;
                    af[mt][kt][0] = *(const uint32_t*)(H + r0 * HS + c0 * 2);
                    af[mt][kt][1] = *(const uint32_t*)(H + r1 * HS + c0 * 2);
                    af[mt][kt][2] = *(const uint32_t*)(H + r0 * HS + (c0 + 8) * 2);
                    af[mt][kt][3] = *(const uint32_t*)(H + r1 * HS + (c0 + 8) * 2);
                }
            }
#pragma unroll
            for (int s = 0; s < 4; s++) {
                float d[2][4][4] = {};
#pragma unroll
                for (int kt = 0; kt < 8; kt++) {
                    uint32_t bf[4][2];
#pragma unroll
                    for (int nt = 0; nt < 4; nt++) {
                        int nn = s * 32 + nt * 8 + q;
                        int kk = kt * 16 + 2 * cpair;
                        bf[nt][0] = *(const uint32_t*)(W2T + nn * W2S + kk * 2);
                        bf[nt][1] = *(const uint32_t*)(W2T + nn * W2S + (kk + 8) * 2);
                    }
#pragma unroll
                    for (int nt = 0; nt < 4; nt++) {
                        mma16816(d[0][nt], af[0][kt], bf[nt]);
                        mma16816(d[1][nt], af[1][kt], bf[nt]);
                    }
                }
#pragma unroll
                for (int nt = 0; nt < 4; nt++) {
                    int col = s * 32 + nt * 8 + 2 * cpair;
                    float2 bb = *(const float2*)(sb2 + col);
                    const float* w3a = sw3 + 3 * col;        // w3[col][0..2]
                    const float* w3b = sw3 + 3 * (col + 1);  // w3[col+1][0..2]
#pragma unroll
                    for (int mt = 0; mt < 2; mt++) {
                        float h00 = fmaxf(d[mt][nt][0] + bb.x, 0.f);
                        float h01 = fmaxf(d[mt][nt][1] + bb.y, 0.f);
                        float h10 = fmaxf(d[mt][nt][2] + bb.x, 0.f);
                        float h11 = fmaxf(d[mt][nt][3] + bb.y, 0.f);
#pragma unroll
                        for (int c = 0; c < 3; c++) {
                            o[2 * mt + 0][c] = fmaf(h00, w3a[c], fmaf(h01, w3b[c], o[2 * mt + 0][c]));
                            o[2 * mt + 1][c] = fmaf(h10, w3a[c], fmaf(h11, w3b[c], o[2 * mt + 1][c]));
                        }
                    }
                }
            }
        }

        // quad reduction: sum partial outputs across the 4 lanes sharing a row
#pragma unroll
        for (int v = 0; v < 4; v++)
#pragma unroll
            for (int c = 0; c < 3; c++) {
                float x = o[v][c];
                x += __shfl_xor_sync(0xffffffffu, x, 1);
                x += __shfl_xor_sync(0xffffffffu, x, 2);
                o[v][c] = x;
            }

        if (cpair == 0) {
            const int rows[4] = { q, q + 8, q + 16, q + 24 };
#pragma unroll
            for (int v = 0; v < 4; v++) {
                int row = t * TILE + wid * 32 + rows[v];
                if (row < n) {
                    out[3 * row + 0] = 1.f / (1.f + __expf(-(o[v][0] + sb3[0])));
                    out[3 * row + 1] = 1.f / (1.f + __expf(-(o[v][1] + sb3[1])));
                    out[3 * row + 2] = 1.f / (1.f + __expf(-(o[v][2] + sb3[2])));
                }
            }
        }
    }
}

extern "C" void kernel_launch(void* const* d_in, const int* in_sizes, int n_in,
                              void* d_out, int out_size)
{
    const float2* uv     = (const float2*)d_in[0];
    const float*  tables = (const float*) d_in[1];
    const float*  w1     = (const float*) d_in[2];
    const float*  b1     = (const float*) d_in[3];
    const float*  w2     = (const float*) d_in[4];
    const float*  b2     = (const float*) d_in[5];
    const float*  w3     = (const float*) d_in[6];
    const float*  b3     = (const float*) d_in[7];
    float* out = (float*)d_out;

    int n = in_sizes[0] / 2;
    int ntiles = (n + TILE - 1) / TILE;

    cudaFuncSetAttribute(ngp_mma_kernel,
                         cudaFuncAttributeMaxDynamicSharedMemorySize, DSMEM);

    int grid = 304;                    // 2 persistent CTAs / SM
    if (grid > ntiles) grid = ntiles;

    ngp_mma_kernel<<<grid, CTA, DSMEM>>>(uv, tables, w1, b1, w2, b2, w3, b3, out, n);
}

// round 6
// speedup vs baseline: 3.8982x; 1.1736x over previous
#include <cuda_runtime.h>
#include <cuda_bf16.h>
#include <math.h>
#include <stdint.h>

#define NLEV   16
#define TBITS  20
#define TSZ    (1u << TBITS)
#define TMASK  (TSZ - 1u)
#define PRIME  2654435761u

#define CTA    256
#define TILE   128

#define W1S 80      // W1^T row stride (bytes): 32 bf16 = 64B padded to 80
#define W2S 272     // W2^T row stride: 128 bf16 = 256B padded to 272
#define XS  80      // X row stride: 32 bf16 padded to 80

#define OFF_W1T 0
#define OFF_W2T 10240
#define OFF_X0  45056
#define OFF_X1  55296
#define OFF_B1  65536
#define OFF_B2  66048
#define OFF_W3  66560
#define OFF_B3  68096
#define DSMEM   81920   // padded so exactly 2 CTAs/SM

__device__ __forceinline__ uint32_t smem_u32(const void* p) {
    uint32_t a;
    asm("{ .reg .u64 t; cvta.to.shared.u64 t, %1; cvt.u32.u64 %0, t; }"
        : "=r"(a) : "l"(p));
    return a;
}
__device__ __forceinline__ uint32_t pack_bf16x2(float lo, float hi) {
    __nv_bfloat162 v = __float22bfloat162_rn(make_float2(lo, hi));
    return *(uint32_t*)&v;
}
__device__ __forceinline__ void ldm_x4(uint32_t* r, uint32_t addr) {
    asm volatile("ldmatrix.sync.aligned.m8n8.x4.shared.b16 {%0,%1,%2,%3}, [%4];"
                 : "=r"(r[0]), "=r"(r[1]), "=r"(r[2]), "=r"(r[3]) : "r"(addr));
}
__device__ __forceinline__ void mma16816(float* d, const uint32_t* a, const uint32_t* b) {
    asm volatile(
        "mma.sync.aligned.m16n8k16.row.col.f32.bf16.bf16.f32 "
        "{%0,%1,%2,%3}, {%4,%5,%6,%7}, {%8,%9}, {%0,%1,%2,%3};"
        : "+f"(d[0]), "+f"(d[1]), "+f"(d[2]), "+f"(d[3])
        : "r"(a[0]), "r"(a[1]), "r"(a[2]), "r"(a[3]), "r"(b[0]), "r"(b[1]));
}

// one hash-grid level -> packed bf16x2 feature pair
template <int LVL>
__device__ __forceinline__ uint32_t encode_level(float2 p, const float* tables) {
    const unsigned res = 16u << LVL;
    float px = p.x * (float)res, py = p.y * (float)res;
    float fx = floorf(px), fy = floorf(py);
    float wx = px - fx, wy = py - fy;
    unsigned cx = (unsigned)(int)fx, cy = (unsigned)(int)fy;
    unsigned i00, i01, i10, i11;
    if ((unsigned long long)(res + 1) * (res + 1) <= (1ull << TBITS)) {
        unsigned rp = res + 1u;
        i00 = cx + cy * rp;        i01 = cx + (cy + 1u) * rp;
        i10 = cx + 1u + cy * rp;   i11 = cx + 1u + (cy + 1u) * rp;
    } else {
        unsigned hy0 = cy * PRIME, hy1 = (cy + 1u) * PRIME;
        i00 = (cx ^ hy0) & TMASK;        i01 = (cx ^ hy1) & TMASK;
        i10 = ((cx + 1u) ^ hy0) & TMASK; i11 = ((cx + 1u) ^ hy1) & TMASK;
    }
    const float2* tb = (const float2*)tables + (size_t)LVL * TSZ;
    float2 f00 = __ldg(tb + i00), f01 = __ldg(tb + i01);
    float2 f10 = __ldg(tb + i10), f11 = __ldg(tb + i11);
    float w00 = (1.f - wx) * (1.f - wy), w01 = (1.f - wx) * wy;
    float w10 = wx * (1.f - wy),         w11 = wx * wy;
    float x0 = w00 * f00.x + w01 * f01.x + w10 * f10.x + w11 * f11.x;
    float x1 = w00 * f00.y + w01 * f01.y + w10 * f10.y + w11 * f11.y;
    return pack_bf16x2(x0, x1);
}

__global__ __launch_bounds__(CTA, 2)
void ngp_mma2_kernel(const float2* __restrict__ uv, const float* __restrict__ tables,
                     const float* __restrict__ w1, const float* __restrict__ b1,
                     const float* __restrict__ w2, const float* __restrict__ b2,
                     const float* __restrict__ w3, const float* __restrict__ b3,
                     float* __restrict__ out, int n)
{
    extern __shared__ char smem[];
    const int tid  = threadIdx.x;
    const int wid  = tid >> 5;
    const int lane = tid & 31;
    const int q    = lane >> 2;
    const int c    = lane & 3;

    // ---- stage weights once per persistent CTA ----
    for (int idx = tid; idx < 32 * 128; idx += CTA) {     // W1^T [n=128][k=32]
        int j = idx >> 5, k = idx & 31;
        *(__nv_bfloat16*)(smem + OFF_W1T + j * W1S + k * 2) = __float2bfloat16(w1[k * 128 + j]);
    }
    for (int idx = tid; idx < 128 * 128; idx += CTA) {    // W2^T [n=128][k=128]
        int j = idx >> 7, k = idx & 127;
        *(__nv_bfloat16*)(smem + OFF_W2T + j * W2S + k * 2) = __float2bfloat16(w2[k * 128 + j]);
    }
    float* sb1 = (float*)(smem + OFF_B1);
    float* sb2 = (float*)(smem + OFF_B2);
    float* sw3 = (float*)(smem + OFF_W3);
    float* sb3 = (float*)(smem + OFF_B3);
    for (int i = tid; i < 128; i += CTA) { sb1[i] = b1[i]; sb2[i] = b2[i]; }
    for (int i = tid; i < 384; i += CTA) sw3[i] = w3[i];
    if (tid < 3) sb3[tid] = b3[tid];
    __syncthreads();

    // lane-constant ldmatrix address parts
    const uint32_t sW1 = smem_u32(smem + OFF_W1T);
    const uint32_t sW2 = smem_u32(smem + OFF_W2T);
    const uint32_t sX0 = smem_u32(smem + OFF_X0);
    const uint32_t sX1 = smem_u32(smem + OFF_X1);
    const int rA = wid * 16 + (lane & 7) + ((lane >> 3) & 1) * 8;
    const uint32_t offA  = (uint32_t)(rA * XS) + ((lane >> 4) * 16);   // X A-frag
    const uint32_t offB1 = (uint32_t)((lane & 7) * W1S) + ((lane >> 3) * 16);
    const uint32_t offB2 = (uint32_t)((lane & 7) * W2S) + ((lane >> 3) * 16);

    const int pt   = tid & 127;      // point within tile this thread encodes
    const int half = tid >> 7;       // 0: levels 0-7, 1: levels 8-15 (warp-uniform)

    const int ntiles = (n + TILE - 1) / TILE;
    int it = 0;
    for (int t = blockIdx.x; t < ntiles; t += gridDim.x, it ^= 1) {
        const uint32_t sx = it ? sX1 : sX0;
        char* Xbuf = smem + (it ? OFF_X1 : OFF_X0);

        // ================= encode: 2 threads/point, 8 levels each =================
        {
            int gid = t * TILE + pt;
            float2 p = __ldg(&uv[gid < n ? gid : (n - 1)]);
            uint32_t xr[8];
            if (half == 0) {
                xr[0] = encode_level<0>(p, tables); xr[1] = encode_level<1>(p, tables);
                xr[2] = encode_level<2>(p, tables); xr[3] = encode_level<3>(p, tables);
                xr[4] = encode_level<4>(p, tables); xr[5] = encode_level<5>(p, tables);
                xr[6] = encode_level<6>(p, tables); xr[7] = encode_level<7>(p, tables);
            } else {
                xr[0] = encode_level<8>(p, tables);  xr[1] = encode_level<9>(p, tables);
                xr[2] = encode_level<10>(p, tables); xr[3] = encode_level<11>(p, tables);
                xr[4] = encode_level<12>(p, tables); xr[5] = encode_level<13>(p, tables);
                xr[6] = encode_level<14>(p, tables); xr[7] = encode_level<15>(p, tables);
            }
            char* dst = Xbuf + pt * XS + half * 32;
            *(uint4*)(dst)      = make_uint4(xr[0], xr[1], xr[2], xr[3]);
            *(uint4*)(dst + 16) = make_uint4(xr[4], xr[5], xr[6], xr[7]);
        }
        __syncthreads();   // the only sync per tile (X double-buffered)

        // ================= layer 1: 16 rows/warp, H -> registers =================
        uint32_t xa[2][4];
        ldm_x4(xa[0], sx + offA);
        ldm_x4(xa[1], sx + offA + 32);

        uint32_t ha[8][4];   // layer-2 A fragments (H), built from D fragments
#pragma unroll
        for (int s = 0; s < 4; s++) {
#pragma unroll
            for (int nt = 0; nt < 4; nt++) {
                const int col0 = s * 32 + nt * 8;
                uint32_t bf[4];
                ldm_x4(bf, sW1 + (uint32_t)(col0 * W1S) + offB1);
                float d[4] = {0.f, 0.f, 0.f, 0.f};
                mma16816(d, xa[0], bf);
                mma16816(d, xa[1], bf + 2);
                float2 bb = *(const float2*)(sb1 + col0 + 2 * c);
                float h0 = fmaxf(d[0] + bb.x, 0.f);
                float h1 = fmaxf(d[1] + bb.y, 0.f);
                float h2 = fmaxf(d[2] + bb.x, 0.f);
                float h3 = fmaxf(d[3] + bb.y, 0.f);
                const int K = 2 * s + (nt >> 1);
                if (nt & 1) { ha[K][2] = pack_bf16x2(h0, h1); ha[K][3] = pack_bf16x2(h2, h3); }
                else        { ha[K][0] = pack_bf16x2(h0, h1); ha[K][1] = pack_bf16x2(h2, h3); }
            }
        }

        // ============ layer 2 (H @ W2) fused with layer 3 accumulation ============
        float oA0 = 0.f, oA1 = 0.f, oA2 = 0.f;   // row q
        float oB0 = 0.f, oB1 = 0.f, oB2 = 0.f;   // row q+8
#pragma unroll
        for (int s = 0; s < 4; s++) {
#pragma unroll
            for (int nt = 0; nt < 4; nt++) {
                const int col0 = s * 32 + nt * 8;
                float d[4] = {0.f, 0.f, 0.f, 0.f};
#pragma unroll
                for (int ktp = 0; ktp < 4; ktp++) {
                    uint32_t bf[4];
                    ldm_x4(bf, sW2 + (uint32_t)(col0 * W2S) + ktp * 64 + offB2);
                    mma16816(d, ha[2 * ktp],     bf);
                    mma16816(d, ha[2 * ktp + 1], bf + 2);
                }
                float2 bb = *(const float2*)(sb2 + col0 + 2 * c);
                float h0 = fmaxf(d[0] + bb.x, 0.f);
                float h1 = fmaxf(d[1] + bb.y, 0.f);
                float h2 = fmaxf(d[2] + bb.x, 0.f);
                float h3 = fmaxf(d[3] + bb.y, 0.f);
                const float* w3a = sw3 + 3 * (col0 + 2 * c);
                const float* w3b = w3a + 3;
                oA0 = fmaf(h0, w3a[0], fmaf(h1, w3b[0], oA0));
                oA1 = fmaf(h0, w3a[1], fmaf(h1, w3b[1], oA1));
                oA2 = fmaf(h0, w3a[2], fmaf(h1, w3b[2], oA2));
                oB0 = fmaf(h2, w3a[0], fmaf(h3, w3b[0], oB0));
                oB1 = fmaf(h2, w3a[1], fmaf(h3, w3b[1], oB1));
                oB2 = fmaf(h2, w3a[2], fmaf(h3, w3b[2], oB2));
            }
        }

        // quad reduction across cpair lanes
#pragma unroll
        for (int m = 1; m <= 2; m <<= 1) {
            oA0 += __shfl_xor_sync(0xffffffffu, oA0, m);
            oA1 += __shfl_xor_sync(0xffffffffu, oA1, m);
            oA2 += __shfl_xor_sync(0xffffffffu, oA2, m);
            oB0 += __shfl_xor_sync(0xffffffffu, oB0, m);
            oB1 += __shfl_xor_sync(0xffffffffu, oB1, m);
            oB2 += __shfl_xor_sync(0xffffffffu, oB2, m);
        }

        if (c == 0) {
            int row0 = t * TILE + wid * 16 + q;
            int row1 = row0 + 8;
            if (row0 < n) {
                out[3 * row0 + 0] = 1.f / (1.f + __expf(-(oA0 + sb3[0])));
                out[3 * row0 + 1] = 1.f / (1.f + __expf(-(oA1 + sb3[1])));
                out[3 * row0 + 2] = 1.f / (1.f + __expf(-(oA2 + sb3[2])));
            }
            if (row1 < n) {
                out[3 * row1 + 0] = 1.f / (1.f + __expf(-(oB0 + sb3[0])));
                out[3 * row1 + 1] = 1.f / (1.f + __expf(-(oB1 + sb3[1])));
                out[3 * row1 + 2] = 1.f / (1.f + __expf(-(oB2 + sb3[2])));
            }
        }
    }
}

extern "C" void kernel_launch(void* const* d_in, const int* in_sizes, int n_in,
                              void* d_out, int out_size)
{
    const float2* uv     = (const float2*)d_in[0];
    const float*  tables = (const float*) d_in[1];
    const float*  w1     = (const float*) d_in[2];
    const float*  b1     = (const float*) d_in[3];
    const float*  w2     = (const float*) d_in[4];
    const float*  b2     = (const float*) d_in[5];
    const float*  w3     = (const float*) d_in[6];
    const float*  b3     = (const float*) d_in[7];
    float* out = (float*)d_out;

    int n = in_sizes[0] / 2;
    int ntiles = (n + TILE - 1) / TILE;

    cudaFuncSetAttribute(ngp_mma2_kernel,
                         cudaFuncAttributeMaxDynamicSharedMemorySize, DSMEM);

    int grid = 304;                 // 2 persistent CTAs / SM
    if (grid > ntiles) grid = ntiles;

    ngp_mma2_kernel<<<grid, CTA, DSMEM>>>(uv, tables, w1, b1, w2, b2, w3, b3, out, n);
}

// round 7
// speedup vs baseline: 5.4284x; 1.3925x over previous
#include <cuda_runtime.h>
#include <cuda_bf16.h>
#include <math.h>
#include <stdint.h>

#define NLEV   16
#define TBITS  20
#define TSZ    (1u << TBITS)
#define TMASK  (TSZ - 1u)
#define PRIME  2654435761u

#define CTA    256
#define TILE   128

#define W1S 80      // W1^T row stride (bytes): 32 bf16 padded to 80
#define W2S 272     // W2^T row stride: 128 bf16 padded to 272
#define XS  80      // X row stride: 32 bf16 padded to 80

#define OFF_W1T 0
#define OFF_W2T 10240
#define OFF_X   45056
#define OFF_B1  55296
#define OFF_B2  55808
#define OFF_W3  56320
#define OFF_B3  57856
#define DSMEM   57984

__device__ __forceinline__ uint32_t smem_u32(const void* p) {
    uint32_t a;
    asm("{ .reg .u64 t; cvta.to.shared.u64 t, %1; cvt.u32.u64 %0, t; }"
        : "=r"(a) : "l"(p));
    return a;
}
__device__ __forceinline__ uint32_t pack_bf16x2(float lo, float hi) {
    __nv_bfloat162 v = __float22bfloat162_rn(make_float2(lo, hi));
    return *(uint32_t*)&v;
}
__device__ __forceinline__ void ldm_x4(uint32_t* r, uint32_t addr) {
    asm volatile("ldmatrix.sync.aligned.m8n8.x4.shared.b16 {%0,%1,%2,%3}, [%4];"
                 : "=r"(r[0]), "=r"(r[1]), "=r"(r[2]), "=r"(r[3]) : "r"(addr));
}
__device__ __forceinline__ void mma16816(float* d, const uint32_t* a, const uint32_t* b) {
    asm volatile(
        "mma.sync.aligned.m16n8k16.row.col.f32.bf16.bf16.f32 "
        "{%0,%1,%2,%3}, {%4,%5,%6,%7}, {%8,%9}, {%0,%1,%2,%3};"
        : "+f"(d[0]), "+f"(d[1]), "+f"(d[2]), "+f"(d[3])
        : "r"(a[0]), "r"(a[1]), "r"(a[2]), "r"(a[3]), "r"(b[0]), "r"(b[1]));
}

__global__ __launch_bounds__(CTA, 2)
void ngp_mma3_kernel(const float2* __restrict__ uv, const float* __restrict__ tables,
                     const float* __restrict__ w1, const float* __restrict__ b1,
                     const float* __restrict__ w2, const float* __restrict__ b2,
                     const float* __restrict__ w3, const float* __restrict__ b3,
                     float* __restrict__ out, int n)
{
    extern __shared__ char smem[];
    const int tid  = threadIdx.x;
    const int wid  = tid >> 5;
    const int lane = tid & 31;
    const int q    = lane >> 2;
    const int c    = lane & 3;

    // ---- stage weights once per persistent CTA ----
    for (int idx = tid; idx < 32 * 128; idx += CTA) {     // W1^T [n=128][k=32]
        int j = idx >> 5, k = idx & 31;
        *(__nv_bfloat16*)(smem + OFF_W1T + j * W1S + k * 2) = __float2bfloat16(w1[k * 128 + j]);
    }
    for (int idx = tid; idx < 128 * 128; idx += CTA) {    // W2^T [n=128][k=128]
        int j = idx >> 7, k = idx & 127;
        *(__nv_bfloat16*)(smem + OFF_W2T + j * W2S + k * 2) = __float2bfloat16(w2[k * 128 + j]);
    }
    float* sb1 = (float*)(smem + OFF_B1);
    float* sb2 = (float*)(smem + OFF_B2);
    float* sw3 = (float*)(smem + OFF_W3);
    float* sb3 = (float*)(smem + OFF_B3);
    for (int i = tid; i < 128; i += CTA) { sb1[i] = b1[i]; sb2[i] = b2[i]; }
    for (int i = tid; i < 384; i += CTA) sw3[i] = w3[i];
    if (tid < 3) sb3[tid] = b3[tid];
    __syncthreads();       // the ONLY CTA-wide sync; X is warp-private below

    const uint32_t sW1 = smem_u32(smem + OFF_W1T);
    const uint32_t sW2 = smem_u32(smem + OFF_W2T);
    const uint32_t sX  = smem_u32(smem + OFF_X);
    char* Xbuf = smem + OFF_X;

    // ldmatrix lane-constant address parts (same mapping validated in R5/R6)
    const int rA = wid * 16 + (lane & 7) + ((lane >> 3) & 1) * 8;
    const uint32_t offA  = (uint32_t)(rA * XS) + ((lane >> 4) * 16);
    const uint32_t offB1 = (uint32_t)((lane & 7) * W1S) + ((lane >> 3) * 16);
    const uint32_t offB2 = (uint32_t)((lane & 7) * W2S) + ((lane >> 3) * 16);

    // corner-parallel encode: lane = 4*psub + corner
    const int corner = lane & 3;            // (ox,oy) = (corner>>1, corner&1)
    const int psub   = lane >> 2;           // 0..7
    const int ox     = corner >> 1;
    const int oy     = corner & 1;

    const int ntiles = (n + TILE - 1) / TILE;
    for (int t = blockIdx.x; t < ntiles; t += gridDim.x) {

        // ============ encode 16 points/warp: 2 groups of 8, 4 lanes/point ============
        __syncwarp();
#pragma unroll
        for (int g = 0; g < 2; g++) {
            const int pt  = wid * 16 + g * 8 + psub;
            const int gid = t * TILE + pt;
            const float2 p = __ldg(&uv[gid < n ? gid : (n - 1)]);
#pragma unroll
            for (int l = 0; l < NLEV; l++) {
                const unsigned res = 16u << l;
                float px = p.x * (float)res, py = p.y * (float)res;
                float fx = floorf(px), fy = floorf(py);
                float wx = px - fx, wy = py - fy;
                unsigned cx = (unsigned)(int)fx + (unsigned)ox;
                unsigned cy = (unsigned)(int)fy + (unsigned)oy;
                unsigned idx;
                if (res <= 512u)          // dense levels 0..5
                    idx = cx + cy * (res + 1u);
                else                      // hash levels 6..15
                    idx = (cx ^ (cy * PRIME)) & TMASK;
                float2 f = __ldg((const float2*)tables + (size_t)l * TSZ + idx);
                float w = (ox ? wx : 1.f - wx) * (oy ? wy : 1.f - wy);
                float v0 = w * f.x, v1 = w * f.y;
                v0 += __shfl_xor_sync(0xffffffffu, v0, 1);
                v1 += __shfl_xor_sync(0xffffffffu, v1, 1);
                v0 += __shfl_xor_sync(0xffffffffu, v0, 2);
                v1 += __shfl_xor_sync(0xffffffffu, v1, 2);
                if (corner == 0)
                    *(uint32_t*)(Xbuf + pt * XS + l * 4) = pack_bf16x2(v0, v1);
            }
        }
        __syncwarp();

        // ================= layer 1: 16 rows/warp, H -> registers =================
        uint32_t xa[2][4];
        ldm_x4(xa[0], sX + offA);
        ldm_x4(xa[1], sX + offA + 32);

        uint32_t ha[8][4];
#pragma unroll
        for (int s = 0; s < 4; s++) {
#pragma unroll
            for (int nt = 0; nt < 4; nt++) {
                const int col0 = s * 32 + nt * 8;
                uint32_t bf[4];
                ldm_x4(bf, sW1 + (uint32_t)(col0 * W1S) + offB1);
                float d[4] = {0.f, 0.f, 0.f, 0.f};
                mma16816(d, xa[0], bf);
                mma16816(d, xa[1], bf + 2);
                float2 bb = *(const float2*)(sb1 + col0 + 2 * c);
                float h0 = fmaxf(d[0] + bb.x, 0.f);
                float h1 = fmaxf(d[1] + bb.y, 0.f);
                float h2 = fmaxf(d[2] + bb.x, 0.f);
                float h3 = fmaxf(d[3] + bb.y, 0.f);
                const int K = 2 * s + (nt >> 1);
                if (nt & 1) { ha[K][2] = pack_bf16x2(h0, h1); ha[K][3] = pack_bf16x2(h2, h3); }
                else        { ha[K][0] = pack_bf16x2(h0, h1); ha[K][1] = pack_bf16x2(h2, h3); }
            }
        }

        // ============ layer 2 (H @ W2) fused with layer 3 accumulation ============
        float oA0 = 0.f, oA1 = 0.f, oA2 = 0.f;
        float oB0 = 0.f, oB1 = 0.f, oB2 = 0.f;
#pragma unroll
        for (int s = 0; s < 4; s++) {
#pragma unroll
            for (int nt = 0; nt < 4; nt++) {
                const int col0 = s * 32 + nt * 8;
                float d[4] = {0.f, 0.f, 0.f, 0.f};
#pragma unroll
                for (int ktp = 0; ktp < 4; ktp++) {
                    uint32_t bf[4];
                    ldm_x4(bf, sW2 + (uint32_t)(col0 * W2S) + ktp * 64 + offB2);
                    mma16816(d, ha[2 * ktp],     bf);
                    mma16816(d, ha[2 * ktp + 1], bf + 2);
                }
                float2 bb = *(const float2*)(sb2 + col0 + 2 * c);
                float h0 = fmaxf(d[0] + bb.x, 0.f);
                float h1 = fmaxf(d[1] + bb.y, 0.f);
                float h2 = fmaxf(d[2] + bb.x, 0.f);
                float h3 = fmaxf(d[3] + bb.y, 0.f);
                const float* w3a = sw3 + 3 * (col0 + 2 * c);
                const float* w3b = w3a + 3;
                oA0 = fmaf(h0, w3a[0], fmaf(h1, w3b[0], oA0));
                oA1 = fmaf(h0, w3a[1], fmaf(h1, w3b[1], oA1));
                oA2 = fmaf(h0, w3a[2], fmaf(h1, w3b[2], oA2));
                oB0 = fmaf(h2, w3a[0], fmaf(h3, w3b[0], oB0));
                oB1 = fmaf(h2, w3a[1], fmaf(h3, w3b[1], oB1));
                oB2 = fmaf(h2, w3a[2], fmaf(h3, w3b[2], oB2));
            }
        }

#pragma unroll
        for (int m = 1; m <= 2; m <<= 1) {
            oA0 += __shfl_xor_sync(0xffffffffu, oA0, m);
            oA1 += __shfl_xor_sync(0xffffffffu, oA1, m);
            oA2 += __shfl_xor_sync(0xffffffffu, oA2, m);
            oB0 += __shfl_xor_sync(0xffffffffu, oB0, m);
            oB1 += __shfl_xor_sync(0xffffffffu, oB1, m);
            oB2 += __shfl_xor_sync(0xffffffffu, oB2, m);
        }

        if (c == 0) {
            int row0 = t * TILE + wid * 16 + q;
            int row1 = row0 + 8;
            if (row0 < n) {
                out[3 * row0 + 0] = 1.f / (1.f + __expf(-(oA0 + sb3[0])));
                out[3 * row0 + 1] = 1.f / (1.f + __expf(-(oA1 + sb3[1])));
                out[3 * row0 + 2] = 1.f / (1.f + __expf(-(oA2 + sb3[2])));
            }
            if (row1 < n) {
                out[3 * row1 + 0] = 1.f / (1.f + __expf(-(oB0 + sb3[0])));
                out[3 * row1 + 1] = 1.f / (1.f + __expf(-(oB1 + sb3[1])));
                out[3 * row1 + 2] = 1.f / (1.f + __expf(-(oB2 + sb3[2])));
            }
        }
    }
}

extern "C" void kernel_launch(void* const* d_in, const int* in_sizes, int n_in,
                              void* d_out, int out_size)
{
    const float2* uv     = (const float2*)d_in[0];
    const float*  tables = (const float*) d_in[1];
    const float*  w1     = (const float*) d_in[2];
    const float*  b1     = (const float*) d_in[3];
    const float*  w2     = (const float*) d_in[4];
    const float*  b2     = (const float*) d_in[5];
    const float*  w3     = (const float*) d_in[6];
    const float*  b3     = (const float*) d_in[7];
    float* out = (float*)d_out;

    int n = in_sizes[0] / 2;
    int ntiles = (n + TILE - 1) / TILE;

    cudaFuncSetAttribute(ngp_mma3_kernel,
                         cudaFuncAttributeMaxDynamicSharedMemorySize, DSMEM);

    int grid = 304;                 // 2 persistent CTAs / SM
    if (grid > ntiles) grid = ntiles;

    ngp_mma3_kernel<<<grid, CTA, DSMEM>>>(uv, tables, w1, b1, w2, b2, w3, b3, out, n);
}